// round 8
// baseline (speedup 1.0000x reference)
#include <cuda_runtime.h>
#include <cuda_fp16.h>

// Capsule routing, B=32, I=1024, O=64, D_in=16, D_out=32.
// R7: uhat = cp.async double-buffered W pipeline (latency was exposed at il
//     boundaries under low occupancy). Squash = 2-stage (red 128->16, then
//     squash) to fix its parallelism starvation (was 23.5us @ occ 6%).
//     Route unchanged (proven 30.2us).

#define B_   32
#define I_   1024
#define O_   64
#define DN   16
#define DD   32
#define OD   2048      // O_*DD
#define CH   8         // capsules (i) per chunk
#define NCH  128       // route partial granularity
#define NR   16        // reduced partial granularity
#define OD4  512

__device__ __half g_uhat [(size_t)B_ * I_ * OD];  // 134 MB (fp16)
__device__ float  g_part [(size_t)NCH * B_ * OD]; // 33.5 MB route partials
__device__ float  g_part2[(size_t)NR * B_ * OD];  // 4.2 MB reduced partials
__device__ float  g_bij  [(size_t)B_ * I_ * O_];  // 8 MB routing logits
__device__ float  g_v    [(size_t)B_ * OD];       // v_j

#define FFMA2(d, a, b, c) \
    asm("fma.rn.f32x2 %0, %1, %2, %3;" : "=l"(d) : "l"(a), "l"(b), "l"(c))
#define MUL2(d, a, b) \
    asm("mul.rn.f32x2 %0, %1, %2;" : "=l"(d) : "l"(a), "l"(b))
#define CP16(dst, src) \
    asm volatile("cp.async.cg.shared.global [%0], [%1], 16;" \
                 :: "r"(dst), "l"(src))
#define CP_COMMIT()  asm volatile("cp.async.commit_group;")
#define CP_WAIT(n)   asm volatile("cp.async.wait_group %0;" :: "n"(n))

// ---------------------------------------------------------------------------
// K1: u_hat (fp16). grid = (4 od-slices, 128 chunks), 128 threads.
// Thread owns 4 od rows. W staged through 2x32KB SMEM buffers via cp.async
// (transposed q-major layout), prefetched one il ahead.
// ---------------------------------------------------------------------------
__global__ __launch_bounds__(128) void k_uhat(const float* __restrict__ x,
                                              const float* __restrict__ W) {
    extern __shared__ float sm[];
    float* xs   = sm;          // CH*B_*DN = 4096 floats (16 KB)
    float* wbuf = sm + 4096;   // 2 x 8192 floats (2 x 32 KB)

    const int tid = threadIdx.x;
    const int od0 = blockIdx.x * 512;
    const int i0  = blockIdx.y * CH;

    // x[:, i0:i0+8, :] -> xs   (layout xs[il][b][n] = [(il*32+b)*16+n])
#pragma unroll
    for (int k = 0; k < 8; k++) {
        const int j  = tid + k * 128;        // float4 index, 1024 total
        const int b  = j >> 5;
        const int r  = j & 31;
        const int il = r >> 2;
        const int nq = r & 3;
        *reinterpret_cast<float4*>(xs + (il * B_ + b) * DN + nq * 4) =
            *reinterpret_cast<const float4*>(
                x + (size_t)b * (I_ * DN) + (i0 + il) * DN + nq * 4);
    }

    const unsigned sbase =
        (unsigned)__cvta_generic_to_shared(wbuf);

    // fill W slice for capsule i into buffer bi (transposed: q-plane major)
    auto fill_w = [&](int bi, int i) {
        const char* gsrc = reinterpret_cast<const char*>(
            W + ((size_t)i * OD + od0) * DN);
        const unsigned dbase = sbase + bi * 32768;
#pragma unroll
        for (int k = 0; k < 16; k++) {       // 2048 16B-chunks / 128 thr
            const int c   = tid + k * 128;
            const int row = c >> 2;
            const int q   = c & 3;
            CP16(dbase + q * 8192 + row * 16, gsrc + c * 16);
        }
        CP_COMMIT();
    };

    fill_w(0, i0);

#pragma unroll 1
    for (int il = 0; il < CH; il++) {
        if (il + 1 < CH) {
            fill_w((il + 1) & 1, i0 + il + 1);
            CP_WAIT(1);
        } else {
            CP_WAIT(0);
        }
        __syncthreads();   // all threads' copies for il visible

        // wp from SMEM (2-way-conflict LDS.128s)
        unsigned long long wp[32];           // wp[r*8 + kp]
        {
            const ulonglong2* wb = reinterpret_cast<const ulonglong2*>(
                wbuf + (il & 1) * 8192);
#pragma unroll
            for (int r = 0; r < 4; r++) {
                const int row = tid * 4 + r;
#pragma unroll
                for (int q = 0; q < 4; q++) {
                    const ulonglong2 lw = wb[q * 512 + row];
                    wp[r * 8 + q * 2]     = lw.x;
                    wp[r * 8 + q * 2 + 1] = lw.y;
                }
            }
        }

        __half* ubase = g_uhat + (size_t)(i0 + il) * OD + od0 + tid * 4;
        const float* xrow = xs + il * (B_ * DN);

#pragma unroll 2
        for (int b = 0; b < B_; b++) {
            const ulonglong2* xq =
                reinterpret_cast<const ulonglong2*>(xrow + b * DN);
            unsigned long long xp[8];
#pragma unroll
            for (int r = 0; r < 4; r++) {
                const ulonglong2 lx = xq[r];
                xp[r * 2 + 0] = lx.x;
                xp[r * 2 + 1] = lx.y;
            }
            unsigned long long acc[4];
#pragma unroll
            for (int od = 0; od < 4; od++) MUL2(acc[od], wp[od * 8], xp[0]);
#pragma unroll
            for (int kp = 1; kp < 8; kp++)
#pragma unroll
                for (int od = 0; od < 4; od++)
                    FFMA2(acc[od], wp[od * 8 + kp], xp[kp], acc[od]);

            const float2 p0 = *reinterpret_cast<float2*>(&acc[0]);
            const float2 p1 = *reinterpret_cast<float2*>(&acc[1]);
            const float2 p2 = *reinterpret_cast<float2*>(&acc[2]);
            const float2 p3 = *reinterpret_cast<float2*>(&acc[3]);
            const __half2 h01 = __floats2half2_rn(p0.x + p0.y, p1.x + p1.y);
            const __half2 h23 = __floats2half2_rn(p2.x + p2.y, p3.x + p3.y);
            uint2 st;
            st.x = *reinterpret_cast<const unsigned*>(&h01);
            st.y = *reinterpret_cast<const unsigned*>(&h23);
            *reinterpret_cast<uint2*>(ubase + (size_t)b * (I_ * OD)) = st;
        }
        __syncthreads();   // done reading wbuf[il&1] before il+2 overwrites
    }
}

// ---------------------------------------------------------------------------
// K1b: fused s0 reduction + squash -> v0. grid = (16, 32), 256 threads.
// ---------------------------------------------------------------------------
__global__ __launch_bounds__(256) void k_s0squash() {
    __shared__ float red[16][128];   // 8 KB
    const int b  = blockIdx.y;
    const int o0 = blockIdx.x * 4;
    const int t  = threadIdx.x;
    const int tq = t & 15;
    const int ig = t >> 4;

    const __half* base = g_uhat + (size_t)b * (I_ * OD) + o0 * DD + tq * 8;
    float r[8] = {0, 0, 0, 0, 0, 0, 0, 0};
#pragma unroll 4
    for (int i = ig; i < I_; i += 16) {
        const uint4 u = *reinterpret_cast<const uint4*>(base + (size_t)i * OD);
        const __half2* h = reinterpret_cast<const __half2*>(&u);
        const float2 f0 = __half22float2(h[0]), f1 = __half22float2(h[1]);
        const float2 f2 = __half22float2(h[2]), f3 = __half22float2(h[3]);
        r[0] += f0.x; r[1] += f0.y; r[2] += f1.x; r[3] += f1.y;
        r[4] += f2.x; r[5] += f2.y; r[6] += f3.x; r[7] += f3.y;
    }
#pragma unroll
    for (int k = 0; k < 8; k++) red[ig][tq * 8 + k] = r[k];
    __syncthreads();

    if (t < 128) {
        float s = 0.f;
#pragma unroll
        for (int g = 0; g < 16; g++) s += red[g][t];
        s *= (1.0f / 64.0f);
        float q = s * s;
#pragma unroll
        for (int sh = 16; sh > 0; sh >>= 1)
            q += __shfl_xor_sync(0xffffffffu, q, sh);
        const float scale = q / (1.f + q) * rsqrtf(q + 1e-8f);
        g_v[(size_t)b * OD + o0 * DD + t] = scale * s;
    }
}

// ---------------------------------------------------------------------------
// K2a: reduce 128 route partials -> 16. grid = (NR, 32), 256 threads.
// ---------------------------------------------------------------------------
__global__ __launch_bounds__(256) void k_red() {
    const int b = blockIdx.y;
    const int r = blockIdx.x;
    const float4* gp = reinterpret_cast<const float4*>(g_part);
    float4* gq = reinterpret_cast<float4*>(g_part2);
#pragma unroll
    for (int k = 0; k < 2; k++) {
        const int c = threadIdx.x + k * 256;
        float4 a = {0, 0, 0, 0};
#pragma unroll
        for (int p = 0; p < 8; p++) {
            const float4 v = gp[((size_t)(r * 8 + p) * B_ + b) * OD4 + c];
            a.x += v.x; a.y += v.y; a.z += v.z; a.w += v.w;
        }
        gq[((size_t)r * B_ + b) * OD4 + c] = a;
    }
}

// ---------------------------------------------------------------------------
// K2b: 16-partial reduce + squash. grid = (4, 32), 128 threads.
// ---------------------------------------------------------------------------
__global__ __launch_bounds__(128) void k_squash(const float* __restrict__ bias,
                                                float* __restrict__ out) {
    const int b    = blockIdx.y;
    const int w    = threadIdx.x >> 5;
    const int lane = threadIdx.x & 31;
    const int o    = blockIdx.x * 16 + w * 4 + (lane >> 3);
    const int dg   = lane & 7;

    const float4* gp = reinterpret_cast<const float4*>(g_part2);
    const size_t base = (size_t)b * OD4 + o * 8 + dg;

    float4 a0 = {0,0,0,0}, a1 = {0,0,0,0}, a2 = {0,0,0,0}, a3 = {0,0,0,0};
#pragma unroll
    for (int t = 0; t < NR; t += 4) {
        float4 p0 = gp[(size_t)(t + 0) * B_ * OD4 + base];
        float4 p1 = gp[(size_t)(t + 1) * B_ * OD4 + base];
        float4 p2 = gp[(size_t)(t + 2) * B_ * OD4 + base];
        float4 p3 = gp[(size_t)(t + 3) * B_ * OD4 + base];
        a0.x += p0.x; a0.y += p0.y; a0.z += p0.z; a0.w += p0.w;
        a1.x += p1.x; a1.y += p1.y; a1.z += p1.z; a1.w += p1.w;
        a2.x += p2.x; a2.y += p2.y; a2.z += p2.z; a2.w += p2.w;
        a3.x += p3.x; a3.y += p3.y; a3.z += p3.z; a3.w += p3.w;
    }
    float4 s;
    s.x = a0.x + a1.x + a2.x + a3.x;
    s.y = a0.y + a1.y + a2.y + a3.y;
    s.z = a0.z + a1.z + a2.z + a3.z;
    s.w = a0.w + a1.w + a2.w + a3.w;
    if (bias) {
        const float4 bb = reinterpret_cast<const float4*>(bias)[o * 8 + dg];
        s.x += bb.x; s.y += bb.y; s.z += bb.z; s.w += bb.w;
    }
    float q = s.x * s.x + s.y * s.y + s.z * s.z + s.w * s.w;
    q += __shfl_xor_sync(0xffffffffu, q, 1);
    q += __shfl_xor_sync(0xffffffffu, q, 2);
    q += __shfl_xor_sync(0xffffffffu, q, 4);
    const float scale = q / (1.f + q) * rsqrtf(q + 1e-8f);
    s.x *= scale; s.y *= scale; s.z *= scale; s.w *= scale;
    float4* dst = reinterpret_cast<float4*>(out ? out : g_v);
    dst[(size_t)b * OD4 + o * 8 + dg] = s;
}

// ---------------------------------------------------------------------------
// K3: one routing pass, register-resident (proven form).
// grid = (128 chunks, 32 batches), 256 threads.
// ---------------------------------------------------------------------------
__global__ __launch_bounds__(256) void k_route(int use_bij_in, int write_bij) {
    __shared__ float sa[CH][O_];
    __shared__ float sc[CH][O_];

    const int b  = blockIdx.y;
    const int i0 = blockIdx.x * CH;
    const int t  = threadIdx.x;
    const int o  = t >> 2;

    const uint4* usrc = reinterpret_cast<const uint4*>(
        g_uhat + ((size_t)b * I_ + i0) * OD) + t;
    uint4 u[CH];
#pragma unroll
    for (int il = 0; il < CH; il++) u[il] = usrc[il * 256];

    const float4* vsrc =
        reinterpret_cast<const float4*>(g_v + (size_t)b * OD) + t * 2;
    const float4 v0 = vsrc[0], v1 = vsrc[1];

#pragma unroll
    for (int il = 0; il < CH; il++) {
        const __half2* h = reinterpret_cast<const __half2*>(&u[il]);
        const float2 f0 = __half22float2(h[0]), f1 = __half22float2(h[1]);
        const float2 f2 = __half22float2(h[2]), f3 = __half22float2(h[3]);
        float a;
        a  = f0.x * v0.x;         a = fmaf(f0.y, v0.y, a);
        a  = fmaf(f1.x, v0.z, a); a = fmaf(f1.y, v0.w, a);
        a  = fmaf(f2.x, v1.x, a); a = fmaf(f2.y, v1.y, a);
        a  = fmaf(f3.x, v1.z, a); a = fmaf(f3.y, v1.w, a);
        a += __shfl_xor_sync(0xffffffffu, a, 1);
        a += __shfl_xor_sync(0xffffffffu, a, 2);
        if ((t & 3) == 0) sa[il][o] = a;
    }
    __syncthreads();

    {
        const int wid  = t >> 5;
        const int lane = t & 31;
        const int i = i0 + wid;
        float a0 = sa[wid][lane];
        float a1 = sa[wid][lane + 32];
        if (use_bij_in) {
            a0 += g_bij[((size_t)b * I_ + i) * O_ + lane];
            a1 += g_bij[((size_t)b * I_ + i) * O_ + lane + 32];
        }
        if (write_bij) {
            g_bij[((size_t)b * I_ + i) * O_ + lane]      = a0;
            g_bij[((size_t)b * I_ + i) * O_ + lane + 32] = a1;
        }
        float m = fmaxf(a0, a1);
#pragma unroll
        for (int s = 16; s > 0; s >>= 1)
            m = fmaxf(m, __shfl_xor_sync(0xffffffffu, m, s));
        const float e0 = __expf(a0 - m);
        const float e1 = __expf(a1 - m);
        float es = e0 + e1;
#pragma unroll
        for (int s = 16; s > 0; s >>= 1)
            es += __shfl_xor_sync(0xffffffffu, es, s);
        const float inv = 1.f / es;
        sc[wid][lane]      = e0 * inv;
        sc[wid][lane + 32] = e1 * inv;
    }
    __syncthreads();

    float4 r0 = {0,0,0,0}, r1 = {0,0,0,0};
#pragma unroll
    for (int il = 0; il < CH; il++) {
        const float s = sc[il][o];
        const __half2* h = reinterpret_cast<const __half2*>(&u[il]);
        const float2 f0 = __half22float2(h[0]), f1 = __half22float2(h[1]);
        const float2 f2 = __half22float2(h[2]), f3 = __half22float2(h[3]);
        r0.x = fmaf(s, f0.x, r0.x); r0.y = fmaf(s, f0.y, r0.y);
        r0.z = fmaf(s, f1.x, r0.z); r0.w = fmaf(s, f1.y, r0.w);
        r1.x = fmaf(s, f2.x, r1.x); r1.y = fmaf(s, f2.y, r1.y);
        r1.z = fmaf(s, f3.x, r1.z); r1.w = fmaf(s, f3.y, r1.w);
    }
    float4* gp = reinterpret_cast<float4*>(
        g_part + ((size_t)blockIdx.x * B_ + b) * OD) + t * 2;
    gp[0] = r0;
    gp[1] = r1;
}

// ---------------------------------------------------------------------------
extern "C" void kernel_launch(void* const* d_in, const int* in_sizes, int n_in,
                              void* d_out, int out_size) {
    const float* x    = (const float*)d_in[0];   // [32,1024,16]
    const float* W    = (const float*)d_in[1];   // [1,1024,64,32,16]
    const float* bias = (const float*)d_in[2];   // [1,1,64,32]
    float* out = (float*)d_out;                  // [32,64,32]

    const int uhat_smem = (4096 + 2 * 8192) * sizeof(float);   // 80 KB
    cudaFuncSetAttribute(k_uhat, cudaFuncAttributeMaxDynamicSharedMemorySize,
                         uhat_smem);

    k_uhat<<<dim3(4, 128), 128, uhat_smem>>>(x, W);   // 1
    k_s0squash<<<dim3(16, 32), 256>>>();              // 2: v0
    k_route<<<dim3(NCH, B_), 256>>>(0, 1);            // 3
    k_red<<<dim3(NR, B_), 256>>>();                   // 4
    k_squash<<<dim3(4, 32), 128>>>(nullptr, nullptr); // 5: v1
    k_route<<<dim3(NCH, B_), 256>>>(1, 0);            // 6 (ncu)
    k_red<<<dim3(NR, B_), 256>>>();                   // 7
    k_squash<<<dim3(4, 32), 128>>>(bias, out);        // 8: out
}

// round 9
// speedup vs baseline: 1.0323x; 1.0323x over previous
#include <cuda_runtime.h>
#include <cuda_fp16.h>

// Capsule routing, B=32, I=1024, O=64, D_in=16, D_out=32.
// R8: k_uhat via HMMA mma.sync.m16n8k16 (M=batch, N=od) -> compute drops to
//     ~2us, uhat becomes memory-bound (~42us). W converted fp32->fp16 in SMEM
//     (cvt cost ~1us chip-wide). Rest = best-known: s0squash, proven route,
//     2-stage red+squash.

#define B_   32
#define I_   1024
#define O_   64
#define DN   16
#define DD   32
#define OD   2048      // O_*DD
#define CH   8         // capsules (i) per route chunk
#define NCH  128       // route partial granularity
#define NR   16        // reduced partial granularity
#define OD4  512

__device__ __half g_uhat [(size_t)B_ * I_ * OD];  // 134 MB (fp16)
__device__ float  g_part [(size_t)NCH * B_ * OD]; // 33.5 MB route partials
__device__ float  g_part2[(size_t)NR * B_ * OD];  // 4.2 MB reduced partials
__device__ float  g_bij  [(size_t)B_ * I_ * O_];  // 8 MB routing logits
__device__ float  g_v    [(size_t)B_ * OD];       // v_j

__device__ __forceinline__ unsigned h2u(const __half2 h) {
    return *reinterpret_cast<const unsigned*>(&h);
}

// ---------------------------------------------------------------------------
// K1: u_hat (fp16) via tensor cores. grid = 1024 (one i per block), 256 thr.
//   C[b=32, od=2048] = A[b=32, k=16] x B[k=16, od=2048]
//   A = x[:, i, :] fp16 (SMEM, frags loaded once); B = W[i] fp16 [od][k].
//   mma.m16n8k16: 2 m-tiles x (8 warps x 32 n-tiles). c0/c1 = 2 consecutive
//   od -> direct half2 store to u_hat.
// ---------------------------------------------------------------------------
__global__ __launch_bounds__(256) void k_uhat(const float* __restrict__ x,
                                              const float* __restrict__ W) {
    extern __shared__ __half sm[];
    __half* wsm = sm;                 // [2048][16] = 64 KB
    __half* xsm = sm + OD * DN;       // [32][16]   = 1 KB

    const int i = blockIdx.x;
    const int t = threadIdx.x;

    // W[i] (2048x16 fp32 = 8192 float4) -> fp16 SMEM, 32 float4 per thread
    const float4* wsrc = reinterpret_cast<const float4*>(W + (size_t)i * (OD * DN));
#pragma unroll
    for (int k = 0; k < 32; k++) {
        const int q = t + (k << 8);
        const float4 f = wsrc[q];
        uint2 st;
        st.x = h2u(__floats2half2_rn(f.x, f.y));
        st.y = h2u(__floats2half2_rn(f.z, f.w));
        *reinterpret_cast<uint2*>(wsm + q * 4) = st;
    }
    // x[:, i, :] (32x16 fp32 = 128 float4) -> fp16 SMEM
    if (t < 128) {
        const int b = t >> 2, kq = t & 3;
        const float4 f = *reinterpret_cast<const float4*>(
            x + (size_t)b * (I_ * DN) + (size_t)i * DN + kq * 4);
        uint2 st;
        st.x = h2u(__floats2half2_rn(f.x, f.y));
        st.y = h2u(__floats2half2_rn(f.z, f.w));
        *reinterpret_cast<uint2*>(xsm + b * DN + kq * 4) = st;
    }
    __syncthreads();

    const int w  = t >> 5;
    const int l  = t & 31;
    const int lq = l >> 2;            // l/4
    const int lr = (l & 3) * 2;       // (l%4)*2

    // A fragments (x), both m-tiles, reused for all 32 n-tiles
    unsigned a[2][4];
#pragma unroll
    for (int mt = 0; mt < 2; mt++) {
        const int bb = mt * 16 + lq;
        a[mt][0] = *reinterpret_cast<const unsigned*>(xsm + bb * DN + lr);
        a[mt][1] = *reinterpret_cast<const unsigned*>(xsm + (bb + 8) * DN + lr);
        a[mt][2] = *reinterpret_cast<const unsigned*>(xsm + bb * DN + lr + 8);
        a[mt][3] = *reinterpret_cast<const unsigned*>(xsm + (bb + 8) * DN + lr + 8);
    }

    __half* ubase = g_uhat + (size_t)i * OD;
#pragma unroll 4
    for (int nt = 0; nt < 32; nt++) {
        const int od0 = w * 256 + nt * 8;
        const unsigned bf0 =
            *reinterpret_cast<const unsigned*>(wsm + (od0 + lq) * DN + lr);
        const unsigned bf1 =
            *reinterpret_cast<const unsigned*>(wsm + (od0 + lq) * DN + lr + 8);
        const int od = od0 + lr;
#pragma unroll
        for (int mt = 0; mt < 2; mt++) {
            float c0 = 0.f, c1 = 0.f, c2 = 0.f, c3 = 0.f;
            asm volatile(
                "mma.sync.aligned.m16n8k16.row.col.f32.f16.f16.f32 "
                "{%0,%1,%2,%3}, {%4,%5,%6,%7}, {%8,%9}, {%0,%1,%2,%3};"
                : "+f"(c0), "+f"(c1), "+f"(c2), "+f"(c3)
                : "r"(a[mt][0]), "r"(a[mt][1]), "r"(a[mt][2]), "r"(a[mt][3]),
                  "r"(bf0), "r"(bf1));
            const int b0 = mt * 16 + lq;
            *reinterpret_cast<unsigned*>(
                ubase + (size_t)b0 * (I_ * OD) + od) =
                h2u(__floats2half2_rn(c0, c1));
            *reinterpret_cast<unsigned*>(
                ubase + (size_t)(b0 + 8) * (I_ * OD) + od) =
                h2u(__floats2half2_rn(c2, c3));
        }
    }
}

// ---------------------------------------------------------------------------
// K1b: fused s0 reduction + squash -> v0. grid = (16, 32), 256 threads.
// ---------------------------------------------------------------------------
__global__ __launch_bounds__(256) void k_s0squash() {
    __shared__ float red[16][128];   // 8 KB
    const int b  = blockIdx.y;
    const int o0 = blockIdx.x * 4;
    const int t  = threadIdx.x;
    const int tq = t & 15;
    const int ig = t >> 4;

    const __half* base = g_uhat + (size_t)b * (I_ * OD) + o0 * DD + tq * 8;
    float r[8] = {0, 0, 0, 0, 0, 0, 0, 0};
#pragma unroll 4
    for (int i = ig; i < I_; i += 16) {
        const uint4 u = *reinterpret_cast<const uint4*>(base + (size_t)i * OD);
        const __half2* h = reinterpret_cast<const __half2*>(&u);
        const float2 f0 = __half22float2(h[0]), f1 = __half22float2(h[1]);
        const float2 f2 = __half22float2(h[2]), f3 = __half22float2(h[3]);
        r[0] += f0.x; r[1] += f0.y; r[2] += f1.x; r[3] += f1.y;
        r[4] += f2.x; r[5] += f2.y; r[6] += f3.x; r[7] += f3.y;
    }
#pragma unroll
    for (int k = 0; k < 8; k++) red[ig][tq * 8 + k] = r[k];
    __syncthreads();

    if (t < 128) {
        float s = 0.f;
#pragma unroll
        for (int g = 0; g < 16; g++) s += red[g][t];
        s *= (1.0f / 64.0f);
        float q = s * s;
#pragma unroll
        for (int sh = 16; sh > 0; sh >>= 1)
            q += __shfl_xor_sync(0xffffffffu, q, sh);
        const float scale = q / (1.f + q) * rsqrtf(q + 1e-8f);
        g_v[(size_t)b * OD + o0 * DD + t] = scale * s;
    }
}

// ---------------------------------------------------------------------------
// K2a: reduce 128 route partials -> 16. grid = (NR, 32), 256 threads.
// ---------------------------------------------------------------------------
__global__ __launch_bounds__(256) void k_red() {
    const int b = blockIdx.y;
    const int r = blockIdx.x;
    const float4* gp = reinterpret_cast<const float4*>(g_part);
    float4* gq = reinterpret_cast<float4*>(g_part2);
#pragma unroll
    for (int k = 0; k < 2; k++) {
        const int c = threadIdx.x + k * 256;
        float4 a = {0, 0, 0, 0};
#pragma unroll
        for (int p = 0; p < 8; p++) {
            const float4 v = gp[((size_t)(r * 8 + p) * B_ + b) * OD4 + c];
            a.x += v.x; a.y += v.y; a.z += v.z; a.w += v.w;
        }
        gq[((size_t)r * B_ + b) * OD4 + c] = a;
    }
}

// ---------------------------------------------------------------------------
// K2b: 16-partial reduce + squash. grid = (4, 32), 128 threads.
// ---------------------------------------------------------------------------
__global__ __launch_bounds__(128) void k_squash(const float* __restrict__ bias,
                                                float* __restrict__ out) {
    const int b    = blockIdx.y;
    const int w    = threadIdx.x >> 5;
    const int lane = threadIdx.x & 31;
    const int o    = blockIdx.x * 16 + w * 4 + (lane >> 3);
    const int dg   = lane & 7;

    const float4* gp = reinterpret_cast<const float4*>(g_part2);
    const size_t base = (size_t)b * OD4 + o * 8 + dg;

    float4 a0 = {0,0,0,0}, a1 = {0,0,0,0}, a2 = {0,0,0,0}, a3 = {0,0,0,0};
#pragma unroll
    for (int t = 0; t < NR; t += 4) {
        float4 p0 = gp[(size_t)(t + 0) * B_ * OD4 + base];
        float4 p1 = gp[(size_t)(t + 1) * B_ * OD4 + base];
        float4 p2 = gp[(size_t)(t + 2) * B_ * OD4 + base];
        float4 p3 = gp[(size_t)(t + 3) * B_ * OD4 + base];
        a0.x += p0.x; a0.y += p0.y; a0.z += p0.z; a0.w += p0.w;
        a1.x += p1.x; a1.y += p1.y; a1.z += p1.z; a1.w += p1.w;
        a2.x += p2.x; a2.y += p2.y; a2.z += p2.z; a2.w += p2.w;
        a3.x += p3.x; a3.y += p3.y; a3.z += p3.z; a3.w += p3.w;
    }
    float4 s;
    s.x = a0.x + a1.x + a2.x + a3.x;
    s.y = a0.y + a1.y + a2.y + a3.y;
    s.z = a0.z + a1.z + a2.z + a3.z;
    s.w = a0.w + a1.w + a2.w + a3.w;
    if (bias) {
        const float4 bb = reinterpret_cast<const float4*>(bias)[o * 8 + dg];
        s.x += bb.x; s.y += bb.y; s.z += bb.z; s.w += bb.w;
    }
    float q = s.x * s.x + s.y * s.y + s.z * s.z + s.w * s.w;
    q += __shfl_xor_sync(0xffffffffu, q, 1);
    q += __shfl_xor_sync(0xffffffffu, q, 2);
    q += __shfl_xor_sync(0xffffffffu, q, 4);
    const float scale = q / (1.f + q) * rsqrtf(q + 1e-8f);
    s.x *= scale; s.y *= scale; s.z *= scale; s.w *= scale;
    float4* dst = reinterpret_cast<float4*>(out ? out : g_v);
    dst[(size_t)b * OD4 + o * 8 + dg] = s;
}

// ---------------------------------------------------------------------------
// K3: one routing pass, register-resident (proven form).
// grid = (128 chunks, 32 batches), 256 threads.
// ---------------------------------------------------------------------------
__global__ __launch_bounds__(256) void k_route(int use_bij_in, int write_bij) {
    __shared__ float sa[CH][O_];
    __shared__ float sc[CH][O_];

    const int b  = blockIdx.y;
    const int i0 = blockIdx.x * CH;
    const int t  = threadIdx.x;
    const int o  = t >> 2;

    const uint4* usrc = reinterpret_cast<const uint4*>(
        g_uhat + ((size_t)b * I_ + i0) * OD) + t;
    uint4 u[CH];
#pragma unroll
    for (int il = 0; il < CH; il++) u[il] = usrc[il * 256];

    const float4* vsrc =
        reinterpret_cast<const float4*>(g_v + (size_t)b * OD) + t * 2;
    const float4 v0 = vsrc[0], v1 = vsrc[1];

#pragma unroll
    for (int il = 0; il < CH; il++) {
        const __half2* h = reinterpret_cast<const __half2*>(&u[il]);
        const float2 f0 = __half22float2(h[0]), f1 = __half22float2(h[1]);
        const float2 f2 = __half22float2(h[2]), f3 = __half22float2(h[3]);
        float a;
        a  = f0.x * v0.x;         a = fmaf(f0.y, v0.y, a);
        a  = fmaf(f1.x, v0.z, a); a = fmaf(f1.y, v0.w, a);
        a  = fmaf(f2.x, v1.x, a); a = fmaf(f2.y, v1.y, a);
        a  = fmaf(f3.x, v1.z, a); a = fmaf(f3.y, v1.w, a);
        a += __shfl_xor_sync(0xffffffffu, a, 1);
        a += __shfl_xor_sync(0xffffffffu, a, 2);
        if ((t & 3) == 0) sa[il][o] = a;
    }
    __syncthreads();

    {
        const int wid  = t >> 5;
        const int lane = t & 31;
        const int i = i0 + wid;
        float a0 = sa[wid][lane];
        float a1 = sa[wid][lane + 32];
        if (use_bij_in) {
            a0 += g_bij[((size_t)b * I_ + i) * O_ + lane];
            a1 += g_bij[((size_t)b * I_ + i) * O_ + lane + 32];
        }
        if (write_bij) {
            g_bij[((size_t)b * I_ + i) * O_ + lane]      = a0;
            g_bij[((size_t)b * I_ + i) * O_ + lane + 32] = a1;
        }
        float m = fmaxf(a0, a1);
#pragma unroll
        for (int s = 16; s > 0; s >>= 1)
            m = fmaxf(m, __shfl_xor_sync(0xffffffffu, m, s));
        const float e0 = __expf(a0 - m);
        const float e1 = __expf(a1 - m);
        float es = e0 + e1;
#pragma unroll
        for (int s = 16; s > 0; s >>= 1)
            es += __shfl_xor_sync(0xffffffffu, es, s);
        const float inv = 1.f / es;
        sc[wid][lane]      = e0 * inv;
        sc[wid][lane + 32] = e1 * inv;
    }
    __syncthreads();

    float4 r0 = {0,0,0,0}, r1 = {0,0,0,0};
#pragma unroll
    for (int il = 0; il < CH; il++) {
        const float s = sc[il][o];
        const __half2* h = reinterpret_cast<const __half2*>(&u[il]);
        const float2 f0 = __half22float2(h[0]), f1 = __half22float2(h[1]);
        const float2 f2 = __half22float2(h[2]), f3 = __half22float2(h[3]);
        r0.x = fmaf(s, f0.x, r0.x); r0.y = fmaf(s, f0.y, r0.y);
        r0.z = fmaf(s, f1.x, r0.z); r0.w = fmaf(s, f1.y, r0.w);
        r1.x = fmaf(s, f2.x, r1.x); r1.y = fmaf(s, f2.y, r1.y);
        r1.z = fmaf(s, f3.x, r1.z); r1.w = fmaf(s, f3.y, r1.w);
    }
    float4* gp = reinterpret_cast<float4*>(
        g_part + ((size_t)blockIdx.x * B_ + b) * OD) + t * 2;
    gp[0] = r0;
    gp[1] = r1;
}

// ---------------------------------------------------------------------------
extern "C" void kernel_launch(void* const* d_in, const int* in_sizes, int n_in,
                              void* d_out, int out_size) {
    const float* x    = (const float*)d_in[0];   // [32,1024,16]
    const float* W    = (const float*)d_in[1];   // [1,1024,64,32,16]
    const float* bias = (const float*)d_in[2];   // [1,1,64,32]
    float* out = (float*)d_out;                  // [32,64,32]

    const int uhat_smem = (OD * DN + B_ * DN) * sizeof(__half);  // 66560 B
    cudaFuncSetAttribute(k_uhat, cudaFuncAttributeMaxDynamicSharedMemorySize,
                         uhat_smem);

    k_uhat<<<I_, 256, uhat_smem>>>(x, W);             // 1
    k_s0squash<<<dim3(16, 32), 256>>>();              // 2: v0
    k_route<<<dim3(NCH, B_), 256>>>(0, 1);            // 3
    k_red<<<dim3(NR, B_), 256>>>();                   // 4
    k_squash<<<dim3(4, 32), 128>>>(nullptr, nullptr); // 5: v1
    k_route<<<dim3(NCH, B_), 256>>>(1, 0);            // 6 (ncu)
    k_red<<<dim3(NR, B_), 256>>>();                   // 7
    k_squash<<<dim3(4, 32), 128>>>(bias, out);        // 8: out
}

// round 10
// speedup vs baseline: 1.2493x; 1.2102x over previous
#include <cuda_runtime.h>
#include <cuda_fp16.h>

// Capsule routing, B=32, I=1024, O=64, D_in=16, D_out=32.
// R9: HMMA uhat keeps tensor path but stages C through per-warp SMEM slabs
//     so global stores are full-sector STG.128 (store bytes halved). s0squash
//     unroll 8 (MLP). route minBlocks=3.

#define B_   32
#define I_   1024
#define O_   64
#define DN   16
#define DD   32
#define OD   2048      // O_*DD
#define CH   8         // capsules (i) per route chunk
#define NCH  128       // route partial granularity
#define NR   16        // reduced partial granularity
#define OD4  512

__device__ __half g_uhat [(size_t)B_ * I_ * OD];  // 134 MB (fp16)
__device__ float  g_part [(size_t)NCH * B_ * OD]; // 33.5 MB route partials
__device__ float  g_part2[(size_t)NR * B_ * OD];  // 4.2 MB reduced partials
__device__ float  g_bij  [(size_t)B_ * I_ * O_];  // 8 MB routing logits
__device__ float  g_v    [(size_t)B_ * OD];       // v_j

__device__ __forceinline__ unsigned h2u(const __half2 h) {
    return *reinterpret_cast<const unsigned*>(&h);
}

// ---------------------------------------------------------------------------
// K1: u_hat (fp16) via tensor cores. grid = 1024 (one i per block), 256 thr.
//   C[b=32, od=2048] = A[b=32,k=16] x B[k=16,od=2048]; A = x fp16, B = W fp16.
//   Stores staged through per-warp SMEM ([32 b][16 od] chunks) so each global
//   row write is 32 B contiguous (full sectors), via STG.128.
// ---------------------------------------------------------------------------
__global__ __launch_bounds__(256) void k_uhat(const float* __restrict__ x,
                                              const float* __restrict__ W) {
    extern __shared__ __half sm[];
    __half* wsm   = sm;                       // [2048][16] = 64 KB
    __half* xsm   = sm + OD * DN;             // [32][16]   = 1 KB
    __half* stage = sm + OD * DN + B_ * DN;   // 8 warps x [32][16] = 8 KB

    const int i = blockIdx.x;
    const int t = threadIdx.x;

    // W[i] (2048x16 fp32 = 8192 float4) -> fp16 SMEM
    const float4* wsrc = reinterpret_cast<const float4*>(W + (size_t)i * (OD * DN));
#pragma unroll
    for (int k = 0; k < 32; k++) {
        const int q = t + (k << 8);
        const float4 f = wsrc[q];
        uint2 st;
        st.x = h2u(__floats2half2_rn(f.x, f.y));
        st.y = h2u(__floats2half2_rn(f.z, f.w));
        *reinterpret_cast<uint2*>(wsm + q * 4) = st;
    }
    // x[:, i, :] -> fp16 SMEM
    if (t < 128) {
        const int b = t >> 2, kq = t & 3;
        const float4 f = *reinterpret_cast<const float4*>(
            x + (size_t)b * (I_ * DN) + (size_t)i * DN + kq * 4);
        uint2 st;
        st.x = h2u(__floats2half2_rn(f.x, f.y));
        st.y = h2u(__floats2half2_rn(f.z, f.w));
        *reinterpret_cast<uint2*>(xsm + b * DN + kq * 4) = st;
    }
    __syncthreads();

    const int w  = t >> 5;
    const int l  = t & 31;
    const int lq = l >> 2;            // l/4
    const int lr = (l & 3) * 2;       // (l%4)*2

    // A fragments (x), both m-tiles
    unsigned a[2][4];
#pragma unroll
    for (int mt = 0; mt < 2; mt++) {
        const int bb = mt * 16 + lq;
        a[mt][0] = *reinterpret_cast<const unsigned*>(xsm + bb * DN + lr);
        a[mt][1] = *reinterpret_cast<const unsigned*>(xsm + (bb + 8) * DN + lr);
        a[mt][2] = *reinterpret_cast<const unsigned*>(xsm + bb * DN + lr + 8);
        a[mt][3] = *reinterpret_cast<const unsigned*>(xsm + (bb + 8) * DN + lr + 8);
    }

    __half* wslab = stage + w * (B_ * 16);    // [32 b][16 od] halfs
    __half* ubase = g_uhat + (size_t)i * OD;

#pragma unroll 2
    for (int nc = 0; nc < 16; nc++) {         // chunk = 2 n-tiles = 16 od
#pragma unroll
        for (int ntl = 0; ntl < 2; ntl++) {
            const int nt  = nc * 2 + ntl;
            const int od0 = w * 256 + nt * 8;
            const unsigned bf0 =
                *reinterpret_cast<const unsigned*>(wsm + (od0 + lq) * DN + lr);
            const unsigned bf1 =
                *reinterpret_cast<const unsigned*>(wsm + (od0 + lq) * DN + lr + 8);
            const int odl = ntl * 8 + lr;
#pragma unroll
            for (int mt = 0; mt < 2; mt++) {
                float c0 = 0.f, c1 = 0.f, c2 = 0.f, c3 = 0.f;
                asm volatile(
                    "mma.sync.aligned.m16n8k16.row.col.f32.f16.f16.f32 "
                    "{%0,%1,%2,%3}, {%4,%5,%6,%7}, {%8,%9}, {%0,%1,%2,%3};"
                    : "+f"(c0), "+f"(c1), "+f"(c2), "+f"(c3)
                    : "r"(a[mt][0]), "r"(a[mt][1]), "r"(a[mt][2]), "r"(a[mt][3]),
                      "r"(bf0), "r"(bf1));
                const int b0 = mt * 16 + lq;
                *reinterpret_cast<unsigned*>(wslab + b0 * 16 + odl) =
                    h2u(__floats2half2_rn(c0, c1));
                *reinterpret_cast<unsigned*>(wslab + (b0 + 8) * 16 + odl) =
                    h2u(__floats2half2_rn(c2, c3));
            }
        }
        __syncwarp();
        // coalesced flush: rows b, 32 B each; lane l -> (b = l>>1 (+16), half l&1)
        {
            const int br = l >> 1;
            const int hf = (l & 1) * 8;
            const int odg = w * 256 + nc * 16 + hf;
#pragma unroll
            for (int p = 0; p < 2; p++) {
                const int b = br + p * 16;
                const uint4 val =
                    *reinterpret_cast<const uint4*>(wslab + b * 16 + hf);
                *reinterpret_cast<uint4*>(
                    ubase + (size_t)b * (I_ * OD) + odg) = val;
            }
        }
        __syncwarp();
    }
}

// ---------------------------------------------------------------------------
// K1b: fused s0 reduction + squash -> v0. grid = (16, 32), 256 threads.
// ---------------------------------------------------------------------------
__global__ __launch_bounds__(256) void k_s0squash() {
    __shared__ float red[16][128];   // 8 KB
    const int b  = blockIdx.y;
    const int o0 = blockIdx.x * 4;
    const int t  = threadIdx.x;
    const int tq = t & 15;
    const int ig = t >> 4;

    const __half* base = g_uhat + (size_t)b * (I_ * OD) + o0 * DD + tq * 8;
    float r[8] = {0, 0, 0, 0, 0, 0, 0, 0};
#pragma unroll 8
    for (int i = ig; i < I_; i += 16) {
        const uint4 u = *reinterpret_cast<const uint4*>(base + (size_t)i * OD);
        const __half2* h = reinterpret_cast<const __half2*>(&u);
        const float2 f0 = __half22float2(h[0]), f1 = __half22float2(h[1]);
        const float2 f2 = __half22float2(h[2]), f3 = __half22float2(h[3]);
        r[0] += f0.x; r[1] += f0.y; r[2] += f1.x; r[3] += f1.y;
        r[4] += f2.x; r[5] += f2.y; r[6] += f3.x; r[7] += f3.y;
    }
#pragma unroll
    for (int k = 0; k < 8; k++) red[ig][tq * 8 + k] = r[k];
    __syncthreads();

    if (t < 128) {
        float s = 0.f;
#pragma unroll
        for (int g = 0; g < 16; g++) s += red[g][t];
        s *= (1.0f / 64.0f);
        float q = s * s;
#pragma unroll
        for (int sh = 16; sh > 0; sh >>= 1)
            q += __shfl_xor_sync(0xffffffffu, q, sh);
        const float scale = q / (1.f + q) * rsqrtf(q + 1e-8f);
        g_v[(size_t)b * OD + o0 * DD + t] = scale * s;
    }
}

// ---------------------------------------------------------------------------
// K2a: reduce 128 route partials -> 16. grid = (NR, 32), 256 threads.
// ---------------------------------------------------------------------------
__global__ __launch_bounds__(256) void k_red() {
    const int b = blockIdx.y;
    const int r = blockIdx.x;
    const float4* gp = reinterpret_cast<const float4*>(g_part);
    float4* gq = reinterpret_cast<float4*>(g_part2);
#pragma unroll
    for (int k = 0; k < 2; k++) {
        const int c = threadIdx.x + k * 256;
        float4 a = {0, 0, 0, 0};
#pragma unroll
        for (int p = 0; p < 8; p++) {
            const float4 v = gp[((size_t)(r * 8 + p) * B_ + b) * OD4 + c];
            a.x += v.x; a.y += v.y; a.z += v.z; a.w += v.w;
        }
        gq[((size_t)r * B_ + b) * OD4 + c] = a;
    }
}

// ---------------------------------------------------------------------------
// K2b: 16-partial reduce + squash. grid = (4, 32), 128 threads.
// ---------------------------------------------------------------------------
__global__ __launch_bounds__(128) void k_squash(const float* __restrict__ bias,
                                                float* __restrict__ out) {
    const int b    = blockIdx.y;
    const int w    = threadIdx.x >> 5;
    const int lane = threadIdx.x & 31;
    const int o    = blockIdx.x * 16 + w * 4 + (lane >> 3);
    const int dg   = lane & 7;

    const float4* gp = reinterpret_cast<const float4*>(g_part2);
    const size_t base = (size_t)b * OD4 + o * 8 + dg;

    float4 a0 = {0,0,0,0}, a1 = {0,0,0,0}, a2 = {0,0,0,0}, a3 = {0,0,0,0};
#pragma unroll
    for (int t = 0; t < NR; t += 4) {
        float4 p0 = gp[(size_t)(t + 0) * B_ * OD4 + base];
        float4 p1 = gp[(size_t)(t + 1) * B_ * OD4 + base];
        float4 p2 = gp[(size_t)(t + 2) * B_ * OD4 + base];
        float4 p3 = gp[(size_t)(t + 3) * B_ * OD4 + base];
        a0.x += p0.x; a0.y += p0.y; a0.z += p0.z; a0.w += p0.w;
        a1.x += p1.x; a1.y += p1.y; a1.z += p1.z; a1.w += p1.w;
        a2.x += p2.x; a2.y += p2.y; a2.z += p2.z; a2.w += p2.w;
        a3.x += p3.x; a3.y += p3.y; a3.z += p3.z; a3.w += p3.w;
    }
    float4 s;
    s.x = a0.x + a1.x + a2.x + a3.x;
    s.y = a0.y + a1.y + a2.y + a3.y;
    s.z = a0.z + a1.z + a2.z + a3.z;
    s.w = a0.w + a1.w + a2.w + a3.w;
    if (bias) {
        const float4 bb = reinterpret_cast<const float4*>(bias)[o * 8 + dg];
        s.x += bb.x; s.y += bb.y; s.z += bb.z; s.w += bb.w;
    }
    float q = s.x * s.x + s.y * s.y + s.z * s.z + s.w * s.w;
    q += __shfl_xor_sync(0xffffffffu, q, 1);
    q += __shfl_xor_sync(0xffffffffu, q, 2);
    q += __shfl_xor_sync(0xffffffffu, q, 4);
    const float scale = q / (1.f + q) * rsqrtf(q + 1e-8f);
    s.x *= scale; s.y *= scale; s.z *= scale; s.w *= scale;
    float4* dst = reinterpret_cast<float4*>(out ? out : g_v);
    dst[(size_t)b * OD4 + o * 8 + dg] = s;
}

// ---------------------------------------------------------------------------
// K3: one routing pass, register-resident. grid = (128, 32), 256 threads,
// minBlocks=3 (80 regs <= 85-reg cap, no spill expected).
// ---------------------------------------------------------------------------
__global__ __launch_bounds__(256, 3) void k_route(int use_bij_in, int write_bij) {
    __shared__ float sa[CH][O_];
    __shared__ float sc[CH][O_];

    const int b  = blockIdx.y;
    const int i0 = blockIdx.x * CH;
    const int t  = threadIdx.x;
    const int o  = t >> 2;

    const uint4* usrc = reinterpret_cast<const uint4*>(
        g_uhat + ((size_t)b * I_ + i0) * OD) + t;
    uint4 u[CH];
#pragma unroll
    for (int il = 0; il < CH; il++) u[il] = usrc[il * 256];

    const float4* vsrc =
        reinterpret_cast<const float4*>(g_v + (size_t)b * OD) + t * 2;
    const float4 v0 = vsrc[0], v1 = vsrc[1];

#pragma unroll
    for (int il = 0; il < CH; il++) {
        const __half2* h = reinterpret_cast<const __half2*>(&u[il]);
        const float2 f0 = __half22float2(h[0]), f1 = __half22float2(h[1]);
        const float2 f2 = __half22float2(h[2]), f3 = __half22float2(h[3]);
        float a;
        a  = f0.x * v0.x;         a = fmaf(f0.y, v0.y, a);
        a  = fmaf(f1.x, v0.z, a); a = fmaf(f1.y, v0.w, a);
        a  = fmaf(f2.x, v1.x, a); a = fmaf(f2.y, v1.y, a);
        a  = fmaf(f3.x, v1.z, a); a = fmaf(f3.y, v1.w, a);
        a += __shfl_xor_sync(0xffffffffu, a, 1);
        a += __shfl_xor_sync(0xffffffffu, a, 2);
        if ((t & 3) == 0) sa[il][o] = a;
    }
    __syncthreads();

    {
        const int wid  = t >> 5;
        const int lane = t & 31;
        const int i = i0 + wid;
        float a0 = sa[wid][lane];
        float a1 = sa[wid][lane + 32];
        if (use_bij_in) {
            a0 += g_bij[((size_t)b * I_ + i) * O_ + lane];
            a1 += g_bij[((size_t)b * I_ + i) * O_ + lane + 32];
        }
        if (write_bij) {
            g_bij[((size_t)b * I_ + i) * O_ + lane]      = a0;
            g_bij[((size_t)b * I_ + i) * O_ + lane + 32] = a1;
        }
        float m = fmaxf(a0, a1);
#pragma unroll
        for (int s = 16; s > 0; s >>= 1)
            m = fmaxf(m, __shfl_xor_sync(0xffffffffu, m, s));
        const float e0 = __expf(a0 - m);
        const float e1 = __expf(a1 - m);
        float es = e0 + e1;
#pragma unroll
        for (int s = 16; s > 0; s >>= 1)
            es += __shfl_xor_sync(0xffffffffu, es, s);
        const float inv = 1.f / es;
        sc[wid][lane]      = e0 * inv;
        sc[wid][lane + 32] = e1 * inv;
    }
    __syncthreads();

    float4 r0 = {0,0,0,0}, r1 = {0,0,0,0};
#pragma unroll
    for (int il = 0; il < CH; il++) {
        const float s = sc[il][o];
        const __half2* h = reinterpret_cast<const __half2*>(&u[il]);
        const float2 f0 = __half22float2(h[0]), f1 = __half22float2(h[1]);
        const float2 f2 = __half22float2(h[2]), f3 = __half22float2(h[3]);
        r0.x = fmaf(s, f0.x, r0.x); r0.y = fmaf(s, f0.y, r0.y);
        r0.z = fmaf(s, f1.x, r0.z); r0.w = fmaf(s, f1.y, r0.w);
        r1.x = fmaf(s, f2.x, r1.x); r1.y = fmaf(s, f2.y, r1.y);
        r1.z = fmaf(s, f3.x, r1.z); r1.w = fmaf(s, f3.y, r1.w);
    }
    float4* gp = reinterpret_cast<float4*>(
        g_part + ((size_t)blockIdx.x * B_ + b) * OD) + t * 2;
    gp[0] = r0;
    gp[1] = r1;
}

// ---------------------------------------------------------------------------
extern "C" void kernel_launch(void* const* d_in, const int* in_sizes, int n_in,
                              void* d_out, int out_size) {
    const float* x    = (const float*)d_in[0];   // [32,1024,16]
    const float* W    = (const float*)d_in[1];   // [1,1024,64,32,16]
    const float* bias = (const float*)d_in[2];   // [1,1,64,32]
    float* out = (float*)d_out;                  // [32,64,32]

    const int uhat_smem =
        (OD * DN + B_ * DN + 8 * B_ * 16) * sizeof(__half);  // 74752 B
    cudaFuncSetAttribute(k_uhat, cudaFuncAttributeMaxDynamicSharedMemorySize,
                         uhat_smem);

    k_uhat<<<I_, 256, uhat_smem>>>(x, W);             // 1
    k_s0squash<<<dim3(16, 32), 256>>>();              // 2: v0
    k_route<<<dim3(NCH, B_), 256>>>(0, 1);            // 3
    k_red<<<dim3(NR, B_), 256>>>();                   // 4
    k_squash<<<dim3(4, 32), 128>>>(nullptr, nullptr); // 5: v1
    k_route<<<dim3(NCH, B_), 256>>>(1, 0);            // 6
    k_red<<<dim3(NR, B_), 256>>>();                   // 7
    k_squash<<<dim3(4, 32), 128>>>(bias, out);        // 8: out
}

// round 11
// speedup vs baseline: 1.2777x; 1.0228x over previous
#include <cuda_runtime.h>
#include <cuda_fp16.h>

// Capsule routing, B=32, I=1024, O=64, D_in=16, D_out=32.
// R10: fp16 route partials (write+red traffic halved); uhat W-staging is
//      per-warp (no block-wide barrier -> warps pipeline independently).

#define B_   32
#define I_   1024
#define O_   64
#define DN   16
#define DD   32
#define OD   2048      // O_*DD
#define CH   8         // capsules (i) per route chunk
#define NCH  128       // route partial granularity
#define NR   16        // reduced partial granularity
#define OD4  512

__device__ __half g_uhat [(size_t)B_ * I_ * OD];  // 134 MB (fp16)
__device__ __half g_parth[(size_t)NCH * B_ * OD]; // 16.8 MB fp16 partials
__device__ float  g_part2[(size_t)NR * B_ * OD];  // 4.2 MB reduced partials
__device__ float  g_bij  [(size_t)B_ * I_ * O_];  // 8 MB routing logits
__device__ float  g_v    [(size_t)B_ * OD];       // v_j

__device__ __forceinline__ unsigned h2u(const __half2 h) {
    return *reinterpret_cast<const unsigned*>(&h);
}

// ---------------------------------------------------------------------------
// K1: u_hat (fp16) via tensor cores. grid = 1024 (one i per block), 256 thr.
//   C[b=32, od=2048] = A[b=32,k=16] x B[k=16,od=2048]. Per-warp W staging
//   (each warp loads its own 256-od slice; only xsm needs a block barrier).
//   Stores staged through per-warp SMEM slabs -> full-sector STG.128.
// ---------------------------------------------------------------------------
__global__ __launch_bounds__(256) void k_uhat(const float* __restrict__ x,
                                              const float* __restrict__ W) {
    extern __shared__ __half sm[];
    __half* wsm   = sm;                       // [2048][16] = 64 KB
    __half* xsm   = sm + OD * DN;             // [32][16]   = 1 KB
    __half* stage = sm + OD * DN + B_ * DN;   // 8 warps x [32][16] = 8 KB

    const int i = blockIdx.x;
    const int t = threadIdx.x;
    const int w = t >> 5;
    const int l = t & 31;

    // x[:, i, :] -> fp16 SMEM (block-shared, needs one barrier)
    if (t < 128) {
        const int b = t >> 2, kq = t & 3;
        const float4 f = *reinterpret_cast<const float4*>(
            x + (size_t)b * (I_ * DN) + (size_t)i * DN + kq * 4);
        uint2 st;
        st.x = h2u(__floats2half2_rn(f.x, f.y));
        st.y = h2u(__floats2half2_rn(f.z, f.w));
        *reinterpret_cast<uint2*>(xsm + b * DN + kq * 4) = st;
    }
    __syncthreads();

    const int lq = l >> 2;            // l/4
    const int lr = (l & 3) * 2;       // (l%4)*2

    // A fragments (x), both m-tiles
    unsigned a[2][4];
#pragma unroll
    for (int mt = 0; mt < 2; mt++) {
        const int bb = mt * 16 + lq;
        a[mt][0] = *reinterpret_cast<const unsigned*>(xsm + bb * DN + lr);
        a[mt][1] = *reinterpret_cast<const unsigned*>(xsm + (bb + 8) * DN + lr);
        a[mt][2] = *reinterpret_cast<const unsigned*>(xsm + bb * DN + lr + 8);
        a[mt][3] = *reinterpret_cast<const unsigned*>(xsm + (bb + 8) * DN + lr + 8);
    }

    // W[i] rows [w*256, (w+1)*256) -> fp16 SMEM (per-warp, no block barrier)
    const float4* wsrc = reinterpret_cast<const float4*>(W + (size_t)i * (OD * DN));
#pragma unroll
    for (int k = 0; k < 32; k++) {
        const int q = (w << 10) + (k << 5) + l;
        const float4 f = wsrc[q];
        uint2 st;
        st.x = h2u(__floats2half2_rn(f.x, f.y));
        st.y = h2u(__floats2half2_rn(f.z, f.w));
        *reinterpret_cast<uint2*>(wsm + q * 4) = st;
    }
    __syncwarp();

    __half* wslab = stage + w * (B_ * 16);    // [32 b][16 od] halfs
    __half* ubase = g_uhat + (size_t)i * OD;

#pragma unroll 2
    for (int nc = 0; nc < 16; nc++) {         // chunk = 2 n-tiles = 16 od
#pragma unroll
        for (int ntl = 0; ntl < 2; ntl++) {
            const int nt  = nc * 2 + ntl;
            const int od0 = w * 256 + nt * 8;
            const unsigned bf0 =
                *reinterpret_cast<const unsigned*>(wsm + (od0 + lq) * DN + lr);
            const unsigned bf1 =
                *reinterpret_cast<const unsigned*>(wsm + (od0 + lq) * DN + lr + 8);
            const int odl = ntl * 8 + lr;
#pragma unroll
            for (int mt = 0; mt < 2; mt++) {
                float c0 = 0.f, c1 = 0.f, c2 = 0.f, c3 = 0.f;
                asm volatile(
                    "mma.sync.aligned.m16n8k16.row.col.f32.f16.f16.f32 "
                    "{%0,%1,%2,%3}, {%4,%5,%6,%7}, {%8,%9}, {%0,%1,%2,%3};"
                    : "+f"(c0), "+f"(c1), "+f"(c2), "+f"(c3)
                    : "r"(a[mt][0]), "r"(a[mt][1]), "r"(a[mt][2]), "r"(a[mt][3]),
                      "r"(bf0), "r"(bf1));
                const int b0 = mt * 16 + lq;
                *reinterpret_cast<unsigned*>(wslab + b0 * 16 + odl) =
                    h2u(__floats2half2_rn(c0, c1));
                *reinterpret_cast<unsigned*>(wslab + (b0 + 8) * 16 + odl) =
                    h2u(__floats2half2_rn(c2, c3));
            }
        }
        __syncwarp();
        {
            const int br = l >> 1;
            const int hf = (l & 1) * 8;
            const int odg = w * 256 + nc * 16 + hf;
#pragma unroll
            for (int p = 0; p < 2; p++) {
                const int b = br + p * 16;
                const uint4 val =
                    *reinterpret_cast<const uint4*>(wslab + b * 16 + hf);
                *reinterpret_cast<uint4*>(
                    ubase + (size_t)b * (I_ * OD) + odg) = val;
            }
        }
        __syncwarp();
    }
}

// ---------------------------------------------------------------------------
// K1b: fused s0 reduction + squash -> v0. grid = (16, 32), 256 threads.
// ---------------------------------------------------------------------------
__global__ __launch_bounds__(256) void k_s0squash() {
    __shared__ float red[16][128];   // 8 KB
    const int b  = blockIdx.y;
    const int o0 = blockIdx.x * 4;
    const int t  = threadIdx.x;
    const int tq = t & 15;
    const int ig = t >> 4;

    const __half* base = g_uhat + (size_t)b * (I_ * OD) + o0 * DD + tq * 8;
    float r[8] = {0, 0, 0, 0, 0, 0, 0, 0};
#pragma unroll 8
    for (int i = ig; i < I_; i += 16) {
        const uint4 u = *reinterpret_cast<const uint4*>(base + (size_t)i * OD);
        const __half2* h = reinterpret_cast<const __half2*>(&u);
        const float2 f0 = __half22float2(h[0]), f1 = __half22float2(h[1]);
        const float2 f2 = __half22float2(h[2]), f3 = __half22float2(h[3]);
        r[0] += f0.x; r[1] += f0.y; r[2] += f1.x; r[3] += f1.y;
        r[4] += f2.x; r[5] += f2.y; r[6] += f3.x; r[7] += f3.y;
    }
#pragma unroll
    for (int k = 0; k < 8; k++) red[ig][tq * 8 + k] = r[k];
    __syncthreads();

    if (t < 128) {
        float s = 0.f;
#pragma unroll
        for (int g = 0; g < 16; g++) s += red[g][t];
        s *= (1.0f / 64.0f);
        float q = s * s;
#pragma unroll
        for (int sh = 16; sh > 0; sh >>= 1)
            q += __shfl_xor_sync(0xffffffffu, q, sh);
        const float scale = q / (1.f + q) * rsqrtf(q + 1e-8f);
        g_v[(size_t)b * OD + o0 * DD + t] = scale * s;
    }
}

// ---------------------------------------------------------------------------
// K2a: reduce 128 fp16 partials -> 16 fp32. grid = (NR, 32), 256 threads.
// Thread covers 8 ods (one uint4 of halfs per partial).
// ---------------------------------------------------------------------------
__global__ __launch_bounds__(256) void k_red() {
    const int b = blockIdx.y;
    const int r = blockIdx.x;
    const int c = threadIdx.x;                 // 256 uint4-chunks per row
    const uint4* gp = reinterpret_cast<const uint4*>(g_parth);

    float4 s0 = {0,0,0,0}, s1 = {0,0,0,0};
#pragma unroll
    for (int p = 0; p < 8; p++) {
        const uint4 u = gp[((size_t)(r * 8 + p) * B_ + b) * 256 + c];
        const __half2* h = reinterpret_cast<const __half2*>(&u);
        const float2 f0 = __half22float2(h[0]), f1 = __half22float2(h[1]);
        const float2 f2 = __half22float2(h[2]), f3 = __half22float2(h[3]);
        s0.x += f0.x; s0.y += f0.y; s0.z += f1.x; s0.w += f1.y;
        s1.x += f2.x; s1.y += f2.y; s1.z += f3.x; s1.w += f3.y;
    }
    float4* gq = reinterpret_cast<float4*>(g_part2) +
                 ((size_t)r * B_ + b) * OD4 + c * 2;
    gq[0] = s0;
    gq[1] = s1;
}

// ---------------------------------------------------------------------------
// K2b: 16-partial reduce + squash. grid = (4, 32), 128 threads.
// ---------------------------------------------------------------------------
__global__ __launch_bounds__(128) void k_squash(const float* __restrict__ bias,
                                                float* __restrict__ out) {
    const int b    = blockIdx.y;
    const int w    = threadIdx.x >> 5;
    const int lane = threadIdx.x & 31;
    const int o    = blockIdx.x * 16 + w * 4 + (lane >> 3);
    const int dg   = lane & 7;

    const float4* gp = reinterpret_cast<const float4*>(g_part2);
    const size_t base = (size_t)b * OD4 + o * 8 + dg;

    float4 a0 = {0,0,0,0}, a1 = {0,0,0,0}, a2 = {0,0,0,0}, a3 = {0,0,0,0};
#pragma unroll
    for (int t = 0; t < NR; t += 4) {
        float4 p0 = gp[(size_t)(t + 0) * B_ * OD4 + base];
        float4 p1 = gp[(size_t)(t + 1) * B_ * OD4 + base];
        float4 p2 = gp[(size_t)(t + 2) * B_ * OD4 + base];
        float4 p3 = gp[(size_t)(t + 3) * B_ * OD4 + base];
        a0.x += p0.x; a0.y += p0.y; a0.z += p0.z; a0.w += p0.w;
        a1.x += p1.x; a1.y += p1.y; a1.z += p1.z; a1.w += p1.w;
        a2.x += p2.x; a2.y += p2.y; a2.z += p2.z; a2.w += p2.w;
        a3.x += p3.x; a3.y += p3.y; a3.z += p3.z; a3.w += p3.w;
    }
    float4 s;
    s.x = a0.x + a1.x + a2.x + a3.x;
    s.y = a0.y + a1.y + a2.y + a3.y;
    s.z = a0.z + a1.z + a2.z + a3.z;
    s.w = a0.w + a1.w + a2.w + a3.w;
    if (bias) {
        const float4 bb = reinterpret_cast<const float4*>(bias)[o * 8 + dg];
        s.x += bb.x; s.y += bb.y; s.z += bb.z; s.w += bb.w;
    }
    float q = s.x * s.x + s.y * s.y + s.z * s.z + s.w * s.w;
    q += __shfl_xor_sync(0xffffffffu, q, 1);
    q += __shfl_xor_sync(0xffffffffu, q, 2);
    q += __shfl_xor_sync(0xffffffffu, q, 4);
    const float scale = q / (1.f + q) * rsqrtf(q + 1e-8f);
    s.x *= scale; s.y *= scale; s.z *= scale; s.w *= scale;
    float4* dst = reinterpret_cast<float4*>(out ? out : g_v);
    dst[(size_t)b * OD4 + o * 8 + dg] = s;
}

// ---------------------------------------------------------------------------
// K3: one routing pass, register-resident, fp16 partial output.
// grid = (128, 32), 256 threads, minBlocks=3.
// ---------------------------------------------------------------------------
__global__ __launch_bounds__(256, 3) void k_route(int use_bij_in, int write_bij) {
    __shared__ float sa[CH][O_];
    __shared__ float sc[CH][O_];

    const int b  = blockIdx.y;
    const int i0 = blockIdx.x * CH;
    const int t  = threadIdx.x;
    const int o  = t >> 2;

    const uint4* usrc = reinterpret_cast<const uint4*>(
        g_uhat + ((size_t)b * I_ + i0) * OD) + t;
    uint4 u[CH];
#pragma unroll
    for (int il = 0; il < CH; il++) u[il] = usrc[il * 256];

    const float4* vsrc =
        reinterpret_cast<const float4*>(g_v + (size_t)b * OD) + t * 2;
    const float4 v0 = vsrc[0], v1 = vsrc[1];

#pragma unroll
    for (int il = 0; il < CH; il++) {
        const __half2* h = reinterpret_cast<const __half2*>(&u[il]);
        const float2 f0 = __half22float2(h[0]), f1 = __half22float2(h[1]);
        const float2 f2 = __half22float2(h[2]), f3 = __half22float2(h[3]);
        float a;
        a  = f0.x * v0.x;         a = fmaf(f0.y, v0.y, a);
        a  = fmaf(f1.x, v0.z, a); a = fmaf(f1.y, v0.w, a);
        a  = fmaf(f2.x, v1.x, a); a = fmaf(f2.y, v1.y, a);
        a  = fmaf(f3.x, v1.z, a); a = fmaf(f3.y, v1.w, a);
        a += __shfl_xor_sync(0xffffffffu, a, 1);
        a += __shfl_xor_sync(0xffffffffu, a, 2);
        if ((t & 3) == 0) sa[il][o] = a;
    }
    __syncthreads();

    {
        const int wid  = t >> 5;
        const int lane = t & 31;
        const int i = i0 + wid;
        float a0 = sa[wid][lane];
        float a1 = sa[wid][lane + 32];
        if (use_bij_in) {
            a0 += g_bij[((size_t)b * I_ + i) * O_ + lane];
            a1 += g_bij[((size_t)b * I_ + i) * O_ + lane + 32];
        }
        if (write_bij) {
            g_bij[((size_t)b * I_ + i) * O_ + lane]      = a0;
            g_bij[((size_t)b * I_ + i) * O_ + lane + 32] = a1;
        }
        float m = fmaxf(a0, a1);
#pragma unroll
        for (int s = 16; s > 0; s >>= 1)
            m = fmaxf(m, __shfl_xor_sync(0xffffffffu, m, s));
        const float e0 = __expf(a0 - m);
        const float e1 = __expf(a1 - m);
        float es = e0 + e1;
#pragma unroll
        for (int s = 16; s > 0; s >>= 1)
            es += __shfl_xor_sync(0xffffffffu, es, s);
        const float inv = 1.f / es;
        sc[wid][lane]      = e0 * inv;
        sc[wid][lane + 32] = e1 * inv;
    }
    __syncthreads();

    float4 r0 = {0,0,0,0}, r1 = {0,0,0,0};
#pragma unroll
    for (int il = 0; il < CH; il++) {
        const float s = sc[il][o];
        const __half2* h = reinterpret_cast<const __half2*>(&u[il]);
        const float2 f0 = __half22float2(h[0]), f1 = __half22float2(h[1]);
        const float2 f2 = __half22float2(h[2]), f3 = __half22float2(h[3]);
        r0.x = fmaf(s, f0.x, r0.x); r0.y = fmaf(s, f0.y, r0.y);
        r0.z = fmaf(s, f1.x, r0.z); r0.w = fmaf(s, f1.y, r0.w);
        r1.x = fmaf(s, f2.x, r1.x); r1.y = fmaf(s, f2.y, r1.y);
        r1.z = fmaf(s, f3.x, r1.z); r1.w = fmaf(s, f3.y, r1.w);
    }
    uint4 st;
    st.x = h2u(__floats2half2_rn(r0.x, r0.y));
    st.y = h2u(__floats2half2_rn(r0.z, r0.w));
    st.z = h2u(__floats2half2_rn(r1.x, r1.y));
    st.w = h2u(__floats2half2_rn(r1.z, r1.w));
    reinterpret_cast<uint4*>(
        g_parth + ((size_t)blockIdx.x * B_ + b) * OD)[t] = st;
}

// ---------------------------------------------------------------------------
extern "C" void kernel_launch(void* const* d_in, const int* in_sizes, int n_in,
                              void* d_out, int out_size) {
    const float* x    = (const float*)d_in[0];   // [32,1024,16]
    const float* W    = (const float*)d_in[1];   // [1,1024,64,32,16]
    const float* bias = (const float*)d_in[2];   // [1,1,64,32]
    float* out = (float*)d_out;                  // [32,64,32]

    const int uhat_smem =
        (OD * DN + B_ * DN + 8 * B_ * 16) * sizeof(__half);  // 74752 B
    cudaFuncSetAttribute(k_uhat, cudaFuncAttributeMaxDynamicSharedMemorySize,
                         uhat_smem);

    k_uhat<<<I_, 256, uhat_smem>>>(x, W);             // 1
    k_s0squash<<<dim3(16, 32), 256>>>();              // 2: v0
    k_route<<<dim3(NCH, B_), 256>>>(0, 1);            // 3
    k_red<<<dim3(NR, B_), 256>>>();                   // 4
    k_squash<<<dim3(4, 32), 128>>>(nullptr, nullptr); // 5: v1
    k_route<<<dim3(NCH, B_), 256>>>(1, 0);            // 6
    k_red<<<dim3(NR, B_), 256>>>();                   // 7
    k_squash<<<dim3(4, 32), 128>>>(bias, out);        // 8: out
}

// round 12
// speedup vs baseline: 1.7172x; 1.3440x over previous
#include <cuda_runtime.h>
#include <cuda_fp16.h>

// Capsule routing, B=32, I=1024, O=64, D_in=16, D_out=32.
// R11: uhat restructured: block = (256-od slice x 8-i chunk); B-fragments
//      loaded DIRECTLY from global W (LDG.64+cvt, sector-perfect; wsm
//      deleted); MMA-C f32 accumulators fused s0 chunk-partials into uhat
//      (s0squash's 134MB re-read eliminated). red+squash merged into k_rsq.
//      6 launches total.

#define B_   32
#define I_   1024
#define O_   64
#define DN   16
#define DD   32
#define OD   2048      // O_*DD
#define CH   8         // capsules (i) per chunk
#define NCH  128       // chunk count / partial granularity
#define SPAD 40        // slab row stride (halfs): conflict-free STS, aligned

__device__ __half g_uhat [(size_t)B_ * I_ * OD];  // 134 MB (fp16)
__device__ __half g_parth[(size_t)NCH * B_ * OD]; // 16.8 MB fp16 partials
__device__ float  g_bij  [(size_t)B_ * I_ * O_];  // 8 MB routing logits
__device__ float  g_v    [(size_t)B_ * OD];       // v_j

__device__ __forceinline__ unsigned h2u(const __half2 h) {
    return *reinterpret_cast<const unsigned*>(&h);
}

// ---------------------------------------------------------------------------
// K1: u_hat (fp16) + s0 chunk partials, via tensor cores.
// grid = (8 od-slices, 128 chunks), 256 threads. Warp w covers 32 od.
// Per i: B-frags straight from global W (LDG.64 + cvt), A-frags from xsm,
// 8 MMAs; C staged through per-warp SMEM slab -> full-sector STG.128.
// f32 accumulators sum C over the 8 i's -> chunk partial to g_parth.
// ---------------------------------------------------------------------------
__global__ __launch_bounds__(256, 3) void k_uhat(const float* __restrict__ x,
                                                 const float* __restrict__ W) {
    __shared__ __half xsm[CH][B_][DN];        // 8 KB
    __shared__ __half slab[8][B_][SPAD];      // 20 KB

    const int t  = threadIdx.x;
    const int w  = t >> 5;
    const int l  = t & 31;
    const int i0  = blockIdx.y * CH;
    const int odw = blockIdx.x * 256 + w * 32;   // warp's global od base

    // x[:, i0:i0+8, :] -> fp16 SMEM. 1024 float4, 4 per thread.
#pragma unroll
    for (int k = 0; k < 4; k++) {
        const int idx = t + k * 256;
        const int b  = idx >> 5;
        const int r  = idx & 31;
        const int il = r >> 2;
        const int kq = r & 3;
        const float4 f = *reinterpret_cast<const float4*>(
            x + (size_t)b * (I_ * DN) + (i0 + il) * DN + kq * 4);
        uint2 st;
        st.x = h2u(__floats2half2_rn(f.x, f.y));
        st.y = h2u(__floats2half2_rn(f.z, f.w));
        *reinterpret_cast<uint2*>(&xsm[il][b][kq * 4]) = st;
    }
    __syncthreads();

    const int lq = l >> 2;            // l/4
    const int lr = (l & 3) * 2;       // (l%4)*2

    float acc[8][4];                  // [nt*2+mt][c] summed over i
#pragma unroll
    for (int j = 0; j < 8; j++)
#pragma unroll
        for (int c = 0; c < 4; c++) acc[j][c] = 0.f;

#pragma unroll 1
    for (int il = 0; il < CH; il++) {
        const int i = i0 + il;

        // A fragments (x[:, i, :])
        unsigned a[2][4];
#pragma unroll
        for (int mt = 0; mt < 2; mt++) {
            const int bb = mt * 16 + lq;
            a[mt][0] = *reinterpret_cast<const unsigned*>(&xsm[il][bb][lr]);
            a[mt][1] = *reinterpret_cast<const unsigned*>(&xsm[il][bb + 8][lr]);
            a[mt][2] = *reinterpret_cast<const unsigned*>(&xsm[il][bb][lr + 8]);
            a[mt][3] = *reinterpret_cast<const unsigned*>(&xsm[il][bb + 8][lr + 8]);
        }

        const float* wbase = W + ((size_t)i * OD + odw) * DN;
#pragma unroll
        for (int nt = 0; nt < 4; nt++) {
            const float* wrow = wbase + (nt * 8 + lq) * DN;
            const float2 f2a = *reinterpret_cast<const float2*>(wrow + lr);
            const float2 f2b = *reinterpret_cast<const float2*>(wrow + lr + 8);
            const unsigned bf0 = h2u(__floats2half2_rn(f2a.x, f2a.y));
            const unsigned bf1 = h2u(__floats2half2_rn(f2b.x, f2b.y));
            const int odl = nt * 8 + lr;
#pragma unroll
            for (int mt = 0; mt < 2; mt++) {
                float c0 = 0.f, c1 = 0.f, c2 = 0.f, c3 = 0.f;
                asm volatile(
                    "mma.sync.aligned.m16n8k16.row.col.f32.f16.f16.f32 "
                    "{%0,%1,%2,%3}, {%4,%5,%6,%7}, {%8,%9}, {%0,%1,%2,%3};"
                    : "+f"(c0), "+f"(c1), "+f"(c2), "+f"(c3)
                    : "r"(a[mt][0]), "r"(a[mt][1]), "r"(a[mt][2]), "r"(a[mt][3]),
                      "r"(bf0), "r"(bf1));
                acc[nt * 2 + mt][0] += c0;
                acc[nt * 2 + mt][1] += c1;
                acc[nt * 2 + mt][2] += c2;
                acc[nt * 2 + mt][3] += c3;
                const int b0 = mt * 16 + lq;
                *reinterpret_cast<unsigned*>(&slab[w][b0][odl]) =
                    h2u(__floats2half2_rn(c0, c1));
                *reinterpret_cast<unsigned*>(&slab[w][b0 + 8][odl]) =
                    h2u(__floats2half2_rn(c2, c3));
            }
        }
        __syncwarp();
        // flush slab -> g_uhat[i]: 32 b-rows x 64 B, 4 lanes per row
#pragma unroll
        for (int p = 0; p < 4; p++) {
            const int b = (l >> 2) + p * 8;
            const uint4 v =
                *reinterpret_cast<const uint4*>(&slab[w][b][(l & 3) * 8]);
            *reinterpret_cast<uint4*>(
                g_uhat + ((size_t)b * I_ + i) * OD + odw + (l & 3) * 8) = v;
        }
        __syncwarp();
    }

    // stage acc -> slab (fp16) -> g_parth chunk partial
#pragma unroll
    for (int nt = 0; nt < 4; nt++) {
        const int odl = nt * 8 + lr;
#pragma unroll
        for (int mt = 0; mt < 2; mt++) {
            const int b0 = mt * 16 + lq;
            *reinterpret_cast<unsigned*>(&slab[w][b0][odl]) =
                h2u(__floats2half2_rn(acc[nt * 2 + mt][0], acc[nt * 2 + mt][1]));
            *reinterpret_cast<unsigned*>(&slab[w][b0 + 8][odl]) =
                h2u(__floats2half2_rn(acc[nt * 2 + mt][2], acc[nt * 2 + mt][3]));
        }
    }
    __syncwarp();
#pragma unroll
    for (int p = 0; p < 4; p++) {
        const int b = (l >> 2) + p * 8;
        const uint4 v =
            *reinterpret_cast<const uint4*>(&slab[w][b][(l & 3) * 8]);
        *reinterpret_cast<uint4*>(
            g_parth + ((size_t)blockIdx.y * B_ + b) * OD + odw + (l & 3) * 8) = v;
    }
}

// ---------------------------------------------------------------------------
// K2: reduce 128 fp16 chunk partials + squash -> g_v or out.
// grid = (16 o-slices, 32 b), 256 threads. Block: batch b, 4 o's (128 od).
// ---------------------------------------------------------------------------
__global__ __launch_bounds__(256) void k_rsq(float factor,
                                             const float* __restrict__ bias,
                                             float* __restrict__ out) {
    __shared__ float red[16][128];   // 8 KB
    const int b  = blockIdx.y;
    const int t  = threadIdx.x;
    const int pg = t >> 4;           // partial group (16)
    const int oc = t & 15;           // uint4 chunk within 128-od slice

    const uint4* gp = reinterpret_cast<const uint4*>(g_parth);
    const size_t base = (size_t)b * 256 + blockIdx.x * 16 + oc;

    float r[8] = {0, 0, 0, 0, 0, 0, 0, 0};
#pragma unroll
    for (int p8 = 0; p8 < 8; p8++) {
        const int p = pg + p8 * 16;
        const uint4 u = gp[(size_t)p * (B_ * 256) + base];
        const __half2* h = reinterpret_cast<const __half2*>(&u);
        const float2 f0 = __half22float2(h[0]), f1 = __half22float2(h[1]);
        const float2 f2 = __half22float2(h[2]), f3 = __half22float2(h[3]);
        r[0] += f0.x; r[1] += f0.y; r[2] += f1.x; r[3] += f1.y;
        r[4] += f2.x; r[5] += f2.y; r[6] += f3.x; r[7] += f3.y;
    }
#pragma unroll
    for (int k = 0; k < 8; k++) red[pg][oc * 8 + k] = r[k];
    __syncthreads();

    if (t < 128) {
        float s = 0.f;
#pragma unroll
        for (int g = 0; g < 16; g++) s += red[g][t];
        s *= factor;
        if (bias) s += bias[blockIdx.x * 128 + t];

        float q = s * s;    // o = t>>5 (warp), d = t&31 (lane)
#pragma unroll
        for (int sh = 16; sh > 0; sh >>= 1)
            q += __shfl_xor_sync(0xffffffffu, q, sh);
        const float scale = q / (1.f + q) * rsqrtf(q + 1e-8f);
        float* dst = out ? out : g_v;
        dst[(size_t)b * OD + blockIdx.x * 128 + t] = scale * s;
    }
}

// ---------------------------------------------------------------------------
// K3: one routing pass, register-resident, fp16 partial output.
// grid = (128, 32), 256 threads, minBlocks=3.
// ---------------------------------------------------------------------------
__global__ __launch_bounds__(256, 3) void k_route(int use_bij_in, int write_bij) {
    __shared__ float sa[CH][O_];
    __shared__ float sc[CH][O_];

    const int b  = blockIdx.y;
    const int i0 = blockIdx.x * CH;
    const int t  = threadIdx.x;
    const int o  = t >> 2;

    const uint4* usrc = reinterpret_cast<const uint4*>(
        g_uhat + ((size_t)b * I_ + i0) * OD) + t;
    uint4 u[CH];
#pragma unroll
    for (int il = 0; il < CH; il++) u[il] = usrc[il * 256];

    const float4* vsrc =
        reinterpret_cast<const float4*>(g_v + (size_t)b * OD) + t * 2;
    const float4 v0 = vsrc[0], v1 = vsrc[1];

#pragma unroll
    for (int il = 0; il < CH; il++) {
        const __half2* h = reinterpret_cast<const __half2*>(&u[il]);
        const float2 f0 = __half22float2(h[0]), f1 = __half22float2(h[1]);
        const float2 f2 = __half22float2(h[2]), f3 = __half22float2(h[3]);
        float a;
        a  = f0.x * v0.x;         a = fmaf(f0.y, v0.y, a);
        a  = fmaf(f1.x, v0.z, a); a = fmaf(f1.y, v0.w, a);
        a  = fmaf(f2.x, v1.x, a); a = fmaf(f2.y, v1.y, a);
        a  = fmaf(f3.x, v1.z, a); a = fmaf(f3.y, v1.w, a);
        a += __shfl_xor_sync(0xffffffffu, a, 1);
        a += __shfl_xor_sync(0xffffffffu, a, 2);
        if ((t & 3) == 0) sa[il][o] = a;
    }
    __syncthreads();

    {
        const int wid  = t >> 5;
        const int lane = t & 31;
        const int i = i0 + wid;
        float a0 = sa[wid][lane];
        float a1 = sa[wid][lane + 32];
        if (use_bij_in) {
            a0 += g_bij[((size_t)b * I_ + i) * O_ + lane];
            a1 += g_bij[((size_t)b * I_ + i) * O_ + lane + 32];
        }
        if (write_bij) {
            g_bij[((size_t)b * I_ + i) * O_ + lane]      = a0;
            g_bij[((size_t)b * I_ + i) * O_ + lane + 32] = a1;
        }
        float m = fmaxf(a0, a1);
#pragma unroll
        for (int s = 16; s > 0; s >>= 1)
            m = fmaxf(m, __shfl_xor_sync(0xffffffffu, m, s));
        const float e0 = __expf(a0 - m);
        const float e1 = __expf(a1 - m);
        float es = e0 + e1;
#pragma unroll
        for (int s = 16; s > 0; s >>= 1)
            es += __shfl_xor_sync(0xffffffffu, es, s);
        const float inv = 1.f / es;
        sc[wid][lane]      = e0 * inv;
        sc[wid][lane + 32] = e1 * inv;
    }
    __syncthreads();

    float4 r0 = {0,0,0,0}, r1 = {0,0,0,0};
#pragma unroll
    for (int il = 0; il < CH; il++) {
        const float s = sc[il][o];
        const __half2* h = reinterpret_cast<const __half2*>(&u[il]);
        const float2 f0 = __half22float2(h[0]), f1 = __half22float2(h[1]);
        const float2 f2 = __half22float2(h[2]), f3 = __half22float2(h[3]);
        r0.x = fmaf(s, f0.x, r0.x); r0.y = fmaf(s, f0.y, r0.y);
        r0.z = fmaf(s, f1.x, r0.z); r0.w = fmaf(s, f1.y, r0.w);
        r1.x = fmaf(s, f2.x, r1.x); r1.y = fmaf(s, f2.y, r1.y);
        r1.z = fmaf(s, f3.x, r1.z); r1.w = fmaf(s, f3.y, r1.w);
    }
    uint4 st;
    st.x = h2u(__floats2half2_rn(r0.x, r0.y));
    st.y = h2u(__floats2half2_rn(r0.z, r0.w));
    st.z = h2u(__floats2half2_rn(r1.x, r1.y));
    st.w = h2u(__floats2half2_rn(r1.z, r1.w));
    reinterpret_cast<uint4*>(
        g_parth + ((size_t)blockIdx.x * B_ + b) * OD)[t] = st;
}

// ---------------------------------------------------------------------------
extern "C" void kernel_launch(void* const* d_in, const int* in_sizes, int n_in,
                              void* d_out, int out_size) {
    const float* x    = (const float*)d_in[0];   // [32,1024,16]
    const float* W    = (const float*)d_in[1];   // [1,1024,64,32,16]
    const float* bias = (const float*)d_in[2];   // [1,1,64,32]
    float* out = (float*)d_out;                  // [32,64,32]

    k_uhat<<<dim3(8, 128), 256>>>(x, W);                  // 1: u_hat + s0 parts
    k_rsq<<<dim3(16, 32), 256>>>(1.f / 64.f, nullptr, nullptr); // 2: v0
    k_route<<<dim3(NCH, B_), 256>>>(0, 1);                // 3
    k_rsq<<<dim3(16, 32), 256>>>(1.f, nullptr, nullptr);  // 4: v1
    k_route<<<dim3(NCH, B_), 256>>>(1, 0);                // 5
    k_rsq<<<dim3(16, 32), 256>>>(1.f, bias, out);         // 6: out
}